// round 6
// baseline (speedup 1.0000x reference)
#include <cuda_runtime.h>
#include <cuda_bf16.h>
#include <cstddef>

// ---------------- problem constants ----------------
#define B_      64
#define T_      512
#define NINP    64
#define NHID    1024
#define THARM   256
#define TSPIKE  256
#define DT_F    0.042f
#define THRESH  0.008f
#define RESET_F 0.001f
#define RC_F    (5.0f * 0.005f)   // R_MEM * C_MEM

#define KS      8          // split-K factor for the recurrent GEMM
#define KC      (NHID/KS)  // 128
#define NBLK    256

// ---------------- device scratch (no cudaMalloc allowed) ----------------
__device__ float g_xw[THARM * B_ * NHID];   // 67 MB: x_t @ x2h (shared by both phases)
__device__ float g_part[KS * B_ * NHID];    // split-K partials (2 MB)
__device__ float g_hy[B_ * NHID];

// grid-barrier state (replay-safe: sense read relatively, count self-resets)
__device__ unsigned g_bar_count = 0;
__device__ unsigned g_bar_sense = 0;

__device__ __forceinline__ void grid_barrier() {
    __syncthreads();
    if (threadIdx.x == 0) {
        volatile unsigned* vs = &g_bar_sense;
        unsigned old = *vs;                 // capture BEFORE arriving
        __threadfence();                    // publish this block's global writes
        if (atomicAdd(&g_bar_count, 1) == NBLK - 1) {
            g_bar_count = 0;
            __threadfence();
            atomicAdd(&g_bar_sense, 1);     // release
        } else {
            while (*vs == old) { }
        }
        __threadfence();
    }
    __syncthreads();
}

// ---------------- K0: g_xw[t][b][h] = x[b,t,:] @ x2h[:,h]  (t < 256) ----------------
__global__ void xw_kernel(const float* __restrict__ x, const float* __restrict__ x2h) {
    __shared__ float xs[64][64];   // [row][k]
    __shared__ float ws[64][64];   // [k][c]
    int tid = threadIdx.x;
    int r0 = blockIdx.x * 64;
    int h0 = blockIdx.y * 64;

    for (int i = tid; i < 64 * 16; i += 256) {
        int row = i >> 4, q = i & 15;
        int r = r0 + row;
        int b = r & 63;
        int t = r >> 6;
        ((float4*)xs[row])[q] =
            ((const float4*)(x + (size_t)b * (T_ * NINP) + (size_t)t * NINP))[q];
    }
    for (int i = tid; i < 64 * 16; i += 256) {
        int k = i >> 4, q = i & 15;
        ((float4*)ws[k])[q] = ((const float4*)(x2h + (size_t)k * NHID + h0))[q];
    }
    __syncthreads();

    int tx = tid & 15, ty = tid >> 4;
    float acc[4][4] = {};
#pragma unroll 16
    for (int k = 0; k < 64; k++) {
        float4 bv = ((float4*)ws[k])[tx];
        float a0 = xs[ty * 4 + 0][k];
        float a1 = xs[ty * 4 + 1][k];
        float a2 = xs[ty * 4 + 2][k];
        float a3 = xs[ty * 4 + 3][k];
        acc[0][0] = fmaf(a0, bv.x, acc[0][0]); acc[0][1] = fmaf(a0, bv.y, acc[0][1]);
        acc[0][2] = fmaf(a0, bv.z, acc[0][2]); acc[0][3] = fmaf(a0, bv.w, acc[0][3]);
        acc[1][0] = fmaf(a1, bv.x, acc[1][0]); acc[1][1] = fmaf(a1, bv.y, acc[1][1]);
        acc[1][2] = fmaf(a1, bv.z, acc[1][2]); acc[1][3] = fmaf(a1, bv.w, acc[1][3]);
        acc[2][0] = fmaf(a2, bv.x, acc[2][0]); acc[2][1] = fmaf(a2, bv.y, acc[2][1]);
        acc[2][2] = fmaf(a2, bv.z, acc[2][2]); acc[2][3] = fmaf(a2, bv.w, acc[2][3]);
        acc[3][0] = fmaf(a3, bv.x, acc[3][0]); acc[3][1] = fmaf(a3, bv.y, acc[3][1]);
        acc[3][2] = fmaf(a3, bv.z, acc[3][2]); acc[3][3] = fmaf(a3, bv.w, acc[3][3]);
    }
#pragma unroll
    for (int i = 0; i < 4; i++) {
        float4 v = make_float4(acc[i][0], acc[i][1], acc[i][2], acc[i][3]);
        ((float4*)(g_xw + (size_t)(r0 + ty * 4 + i) * NHID + h0))[tx] = v;
    }
}

// ---------------- split-K GEMM phase (runs inside persistent kernel) ----------------
// Block (ct, ks): output cols [c0, c0+32), K-chunk [k0, k0+128). sb (h2h tile)
// preloaded once per kernel. hy staged from global (L2-only) each step.
__device__ __forceinline__ void gemm_phase(float (*sa)[KC], const float (*sb)[32],
                                           int k0, int c0, int m0, int lane, int ks) {
    int tid = threadIdx.x;
    for (int i = tid; i < 64 * (KC / 4); i += 256) {
        int row = i >> 5, q = i & 31;
        float4 v = __ldcg(((const float4*)(g_hy + (size_t)row * NHID + k0)) + q);
        ((float4*)sa[row])[q] = v;
    }
    __syncthreads();
    float acc[8] = {};
#pragma unroll 8
    for (int k = 0; k < KC; k += 4) {
        float b0 = sb[k + 0][lane];
        float b1 = sb[k + 1][lane];
        float b2 = sb[k + 2][lane];
        float b3 = sb[k + 3][lane];
#pragma unroll
        for (int r = 0; r < 8; r++) {
            float4 av = *(const float4*)&sa[m0 + r][k];   // LDS.128 broadcast
            acc[r] = fmaf(av.x, b0, acc[r]);
            acc[r] = fmaf(av.y, b1, acc[r]);
            acc[r] = fmaf(av.z, b2, acc[r]);
            acc[r] = fmaf(av.w, b3, acc[r]);
        }
    }
    float* dst = g_part + ((size_t)ks << 16) + c0 + lane;
#pragma unroll
    for (int r = 0; r < 8; r++)
        __stcg(dst + (size_t)(m0 + r) * NHID, acc[r]);
}

// ---------------- persistent kernel: harmonic loop + hyW + spiking + bcast ----------------
__global__ void __launch_bounds__(256, 2) ron_kernel(
        const float* __restrict__ h2h,
        const float* __restrict__ bias,
        const float* __restrict__ gamma,
        const float* __restrict__ eps,
        float* __restrict__ out_hys, float* __restrict__ out_hzs,
        float* __restrict__ out_us,  float* __restrict__ out_spk) {
    __shared__ float sa[64][KC];   // 32 KB: hy slice
    __shared__ float sb[KC][32];   // 16 KB: h2h tile (persistent across steps)

    const int tid = threadIdx.x, bid = blockIdx.x;
    const int ct = bid & 31, ks = bid >> 5;
    const int c0 = ct * 32, k0 = ks * KC;
    const int lane = tid & 31, m0 = (tid >> 5) * 8;

    // preload h2h tile once for all 257 GEMMs
    for (int i = tid; i < KC * 8; i += 256) {
        int k = i >> 3, q = i & 7;
        ((float4*)sb[k])[q] = ((const float4*)(h2h + (size_t)(k0 + k) * NHID + c0))[q];
    }

    // element owned by this thread for the update/spike phases
    const int eidx = (bid << 8) + tid;          // 0..65535
    const int eh = eidx & (NHID - 1);
    const int eb = eidx >> 10;
    const float bia = __ldg(bias + eh);
    const float gam = __ldg(gamma + eh);
    const float ep  = __ldg(eps + eh);

    float hy = 0.0f, hz = 0.0f;

    // ---- t = 0: hy0 = 0, so the GEMM term is 0; update directly ----
    {
        float z = tanhf(g_xw[eidx] + bia);       // t=0 offset is 0
        hz = hz + DT_F * (z - gam * hy - ep * hz);
        hy = hy + DT_F * hz;
        __stcg(g_hy + eidx, hy);
        size_t o = ((size_t)eb * T_ + 0) * NHID + eh;
        out_hys[o] = hy;
        out_hzs[o] = hz;
    }
    grid_barrier();   // publishes g_hy (and orders sb preload via its syncthreads)

    // ---- t = 1 .. THARM-1 ----
    for (int t = 1; t < THARM; t++) {
        gemm_phase(sa, sb, k0, c0, m0, lane, ks);
        grid_barrier();                          // partials visible

        float s = 0.0f;
#pragma unroll
        for (int sI = 0; sI < KS; sI++)
            s += __ldcg(g_part + ((size_t)sI << 16) + eidx);
        float z = tanhf(g_xw[((size_t)t << 16) + eidx] + s + bia);
        hz = hz + DT_F * (z - gam * hy - ep * hz);
        hy = hy + DT_F * hz;
        __stcg(g_hy + eidx, hy);
        size_t o = ((size_t)eb * T_ + t) * NHID + eh;
        out_hys[o] = hy;
        out_hzs[o] = hz;
        grid_barrier();                          // g_hy visible; partials free to overwrite
    }

    // ---- hyW = hy_final @ h2h ----
    gemm_phase(sa, sb, k0, c0, m0, lane, ks);
    grid_barrier();
    float hyw = 0.0f;
#pragma unroll
    for (int sI = 0; sI < KS; sI++)
        hyw += __ldcg(g_part + ((size_t)sI << 16) + eidx);

    // ---- spiking phase + broadcast of frozen hy/hz (all per-element, register state) ----
    float u = 0.0f;
    const size_t ob = (size_t)eb * (TSPIKE * NHID) + eh;
    const size_t hb = ((size_t)eb * T_ + THARM) * NHID + eh;
#pragma unroll 4
    for (int t = 0; t < TSPIKE; t++) {
        float spike = (u > THRESH) ? 1.0f : 0.0f;
        if (spike == 1.0f) u = RESET_F;
        float xw = g_xw[((size_t)t << 16) + eidx];
        u = u + ((-u + hyw + xw) * RC_F) * DT_F;
        size_t so = (size_t)t * NHID;
        out_us[ob + so]  = u;
        out_spk[ob + so] = spike;
        out_hys[hb + so] = hy;
        out_hzs[hb + so] = hz;
    }
}

// ---------------- launcher ----------------
extern "C" void kernel_launch(void* const* d_in, const int* in_sizes, int n_in,
                              void* d_out, int out_size) {
    const float* x     = (const float*)d_in[0];
    const float* x2h   = (const float*)d_in[1];
    const float* h2h   = (const float*)d_in[2];
    const float* bias  = (const float*)d_in[3];
    const float* gamma = (const float*)d_in[4];
    const float* eps   = (const float*)d_in[5];

    float* out = (float*)d_out;
    float* out_hys = out;
    float* out_hzs = out + (size_t)B_ * T_ * NHID;
    float* out_us  = out_hzs + (size_t)B_ * T_ * NHID;
    float* out_spk = out_us + (size_t)B_ * TSPIKE * NHID;

    xw_kernel<<<dim3(256, 16), 256>>>(x, x2h);
    ron_kernel<<<NBLK, 256>>>(h2h, bias, gamma, eps,
                              out_hys, out_hzs, out_us, out_spk);
}

// round 11
// speedup vs baseline: 1.1746x; 1.1746x over previous
#include <cuda_runtime.h>
#include <cuda_bf16.h>
#include <cstddef>

// ---------------- problem constants ----------------
#define B_      64
#define T_      512
#define NINP    64
#define NHID    1024
#define THARM   256
#define TSPIKE  256
#define DT_F    0.042f
#define THRESH  0.008f
#define RESET_F 0.001f
#define RC_F    (5.0f * 0.005f)   // R_MEM * C_MEM

// GEMM decomposition: 256 blocks = 2 m-tiles (32 b) x 8 col-tiles (128 h) x 16 k-chunks (64 k)
#define KS      16
#define KC      64
#define MT      32
#define NT      128
#define NBLK    256

// ---------------- device scratch (no cudaMalloc allowed) ----------------
__device__ float g_xw[THARM * B_ * NHID];   // 67 MB: x_t @ x2h, layout [t][b][h]
__device__ float g_part[KS * B_ * NHID];    // split-K partials, [ks][b][h] (4 MB)
__device__ float g_hyT[NHID * B_];          // hy transposed [h][b] (GEMM A operand)

// grid-barrier state (replay-safe: sense captured relatively, count self-resets)
__device__ unsigned g_bar_count = 0;
__device__ unsigned g_bar_sense = 0;

__device__ __forceinline__ unsigned ld_acquire_gpu(unsigned* p) {
    unsigned v;
    asm volatile("ld.acquire.gpu.u32 %0, [%1];" : "=r"(v) : "l"(p) : "memory");
    return v;
}
__device__ __forceinline__ unsigned ld_relaxed_gpu(unsigned* p) {
    unsigned v;
    asm volatile("ld.relaxed.gpu.u32 %0, [%1];" : "=r"(v) : "l"(p) : "memory");
    return v;
}
__device__ __forceinline__ unsigned atom_add_release_gpu(unsigned* p, unsigned a) {
    unsigned o;
    asm volatile("atom.add.release.gpu.u32 %0, [%1], %2;" : "=r"(o) : "l"(p), "r"(a) : "memory");
    return o;
}
__device__ __forceinline__ void st_relaxed_gpu(unsigned* p, unsigned v) {
    asm volatile("st.relaxed.gpu.u32 [%0], %1;" :: "l"(p), "r"(v) : "memory");
}

__device__ __forceinline__ void grid_barrier() {
    __syncthreads();
    if (threadIdx.x == 0) {
        unsigned sense = ld_relaxed_gpu(&g_bar_sense);     // capture before arriving
        if (atom_add_release_gpu(&g_bar_count, 1u) == NBLK - 1) {
            st_relaxed_gpu(&g_bar_count, 0u);
            atom_add_release_gpu(&g_bar_sense, 1u);        // release (orders count reset too)
        } else {
            while (ld_acquire_gpu(&g_bar_sense) == sense) { }
        }
    }
    __syncthreads();
}

// ---------------- K0: g_xw[t][b][h] = x[b,t,:] @ x2h[:,h]  (t < 256) ----------------
__global__ void xw_kernel(const float* __restrict__ x, const float* __restrict__ x2h) {
    __shared__ float xs[64][64];   // [row][k]
    __shared__ float ws[64][64];   // [k][c]
    int tid = threadIdx.x;
    int r0 = blockIdx.x * 64;
    int h0 = blockIdx.y * 64;

    for (int i = tid; i < 64 * 16; i += 256) {
        int row = i >> 4, q = i & 15;
        int r = r0 + row;
        int b = r & 63;
        int t = r >> 6;
        ((float4*)xs[row])[q] =
            ((const float4*)(x + (size_t)b * (T_ * NINP) + (size_t)t * NINP))[q];
    }
    for (int i = tid; i < 64 * 16; i += 256) {
        int k = i >> 4, q = i & 15;
        ((float4*)ws[k])[q] = ((const float4*)(x2h + (size_t)k * NHID + h0))[q];
    }
    __syncthreads();

    int tx = tid & 15, ty = tid >> 4;
    float acc[4][4] = {};
#pragma unroll 16
    for (int k = 0; k < 64; k++) {
        float4 bv = ((float4*)ws[k])[tx];
        float a0 = xs[ty * 4 + 0][k];
        float a1 = xs[ty * 4 + 1][k];
        float a2 = xs[ty * 4 + 2][k];
        float a3 = xs[ty * 4 + 3][k];
        acc[0][0] = fmaf(a0, bv.x, acc[0][0]); acc[0][1] = fmaf(a0, bv.y, acc[0][1]);
        acc[0][2] = fmaf(a0, bv.z, acc[0][2]); acc[0][3] = fmaf(a0, bv.w, acc[0][3]);
        acc[1][0] = fmaf(a1, bv.x, acc[1][0]); acc[1][1] = fmaf(a1, bv.y, acc[1][1]);
        acc[1][2] = fmaf(a1, bv.z, acc[1][2]); acc[1][3] = fmaf(a1, bv.w, acc[1][3]);
        acc[2][0] = fmaf(a2, bv.x, acc[2][0]); acc[2][1] = fmaf(a2, bv.y, acc[2][1]);
        acc[2][2] = fmaf(a2, bv.z, acc[2][2]); acc[2][3] = fmaf(a2, bv.w, acc[2][3]);
        acc[3][0] = fmaf(a3, bv.x, acc[3][0]); acc[3][1] = fmaf(a3, bv.y, acc[3][1]);
        acc[3][2] = fmaf(a3, bv.z, acc[3][2]); acc[3][3] = fmaf(a3, bv.w, acc[3][3]);
    }
#pragma unroll
    for (int i = 0; i < 4; i++) {
        float4 v = make_float4(acc[i][0], acc[i][1], acc[i][2], acc[i][3]);
        ((float4*)(g_xw + (size_t)(r0 + ty * 4 + i) * NHID + h0))[tx] = v;
    }
}

// ---------------- persistent kernel ----------------
// Block bid: ks = bid&15, ct = (bid>>4)&7, mt = bid>>7.
// GEMM tile: rows b in [mt*32, mt*32+32), cols h in [ct*128, ct*128+128), k in [ks*64, ks*64+64).
// Thread tile 4b x 4h: rg = tid>>5 (8 x 4b), cg = tid&31 (32 x 4h).
__global__ void __launch_bounds__(256, 2) ron_kernel(
        const float* __restrict__ h2h,
        const float* __restrict__ bias,
        const float* __restrict__ gamma,
        const float* __restrict__ eps,
        float* __restrict__ out_hys, float* __restrict__ out_hzs,
        float* __restrict__ out_us,  float* __restrict__ out_spk) {
    __shared__ float sb[KC][NT];   // 32 KB: h2h slice [k][h], persistent all steps
    __shared__ float sa[KC][MT];   // 8 KB:  hyT slice [k][b], staged each step

    const int tid = threadIdx.x, bid = blockIdx.x;
    const int ks = bid & 15;
    const int ct = (bid >> 4) & 7;
    const int mt = bid >> 7;
    const int b0 = mt * MT;
    const int c0 = ct * NT;
    const int k0 = ks * KC;
    const int rg = tid >> 5;       // 0..7  -> rows b0 + 4rg .. +4
    const int cg = tid & 31;       // 0..31 -> cols c0 + 4cg .. +4

    // preload h2h slice once: sb[k][h'] = h2h[k0+k][c0+h']
    for (int i = tid; i < KC * (NT / 4); i += 256) {
        int k = i >> 5, q = i & 31;
        ((float4*)sb[k])[q] = ((const float4*)(h2h + (size_t)(k0 + k) * NHID + c0))[q];
    }

    // element owned by this thread in update/spike phases (h-fast => coalesced I/O)
    const int eidx = (bid << 8) + tid;          // 0..65535 = b*1024 + h
    const int eh = eidx & (NHID - 1);
    const int eb = eidx >> 10;
    const float bia = __ldg(bias + eh);
    const float gam = __ldg(gamma + eh);
    const float ep  = __ldg(eps + eh);

    float hy = 0.0f, hz = 0.0f;

    // ---- t = 0: hy0 = 0 -> recurrent term is 0 ----
    {
        float z = tanhf(g_xw[eidx] + bia);
        hz = hz + DT_F * (z - gam * hy - ep * hz);
        hy = hy + DT_F * hz;
        __stcg(g_hyT + (size_t)eh * B_ + eb, hy);      // transposed store (scattered, small)
        size_t o = ((size_t)eb * T_ + 0) * NHID + eh;
        out_hys[o] = hy;
        out_hzs[o] = hz;
    }
    grid_barrier();

    // ---- steps t = 1..255 and one extra pass (t = 256) to produce hyW ----
    float hyw = 0.0f;
    for (int t = 1; t <= THARM; t++) {
        // prefetch xw for this step (independent of partials)
        float xw = (t < THARM) ? __ldcg(g_xw + ((size_t)t << 16) + eidx) : 0.0f;

        // stage A: sa[k][b'] = g_hyT[k0+k][b0+b']   (coalesced, 8 KB)
        for (int i = tid; i < KC * (MT / 4); i += 256) {
            int k = i >> 3, q = i & 7;
            float4 v = __ldcg((const float4*)(g_hyT + (size_t)(k0 + k) * B_ + b0) + q);
            ((float4*)sa[k])[q] = v;
        }
        __syncthreads();

        float acc[4][4] = {};
#pragma unroll 8
        for (int k = 0; k < KC; k++) {
            float4 av = *(const float4*)&sa[k][rg * 4];   // broadcast within warp (1 wf)
            float4 bv = ((const float4*)sb[k])[cg];       // conflict-free 512B
            acc[0][0] = fmaf(av.x, bv.x, acc[0][0]); acc[0][1] = fmaf(av.x, bv.y, acc[0][1]);
            acc[0][2] = fmaf(av.x, bv.z, acc[0][2]); acc[0][3] = fmaf(av.x, bv.w, acc[0][3]);
            acc[1][0] = fmaf(av.y, bv.x, acc[1][0]); acc[1][1] = fmaf(av.y, bv.y, acc[1][1]);
            acc[1][2] = fmaf(av.y, bv.z, acc[1][2]); acc[1][3] = fmaf(av.y, bv.w, acc[1][3]);
            acc[2][0] = fmaf(av.z, bv.x, acc[2][0]); acc[2][1] = fmaf(av.z, bv.y, acc[2][1]);
            acc[2][2] = fmaf(av.z, bv.z, acc[2][2]); acc[2][3] = fmaf(av.z, bv.w, acc[2][3]);
            acc[3][0] = fmaf(av.w, bv.x, acc[3][0]); acc[3][1] = fmaf(av.w, bv.y, acc[3][1]);
            acc[3][2] = fmaf(av.w, bv.z, acc[3][2]); acc[3][3] = fmaf(av.w, bv.w, acc[3][3]);
        }
        // store partials: g_part[ks][b][h], coalesced float4
        {
            float* dst = g_part + ((size_t)ks << 16) + (size_t)(b0 + rg * 4) * NHID + c0 + cg * 4;
#pragma unroll
            for (int r = 0; r < 4; r++) {
                float4 v = make_float4(acc[r][0], acc[r][1], acc[r][2], acc[r][3]);
                __stcg((float4*)(dst + (size_t)r * NHID), v);
            }
        }
        grid_barrier();                               // partials visible everywhere

        // reduce split-K for owned element
        float s = 0.0f;
#pragma unroll
        for (int sI = 0; sI < KS; sI++)
            s += __ldcg(g_part + ((size_t)sI << 16) + eidx);

        if (t < THARM) {
            float z = tanhf(xw + s + bia);
            hz = hz + DT_F * (z - gam * hy - ep * hz);
            hy = hy + DT_F * hz;
            __stcg(g_hyT + (size_t)eh * B_ + eb, hy);
            size_t o = ((size_t)eb * T_ + t) * NHID + eh;
            out_hys[o] = hy;
            out_hzs[o] = hz;
            grid_barrier();                           // new hy visible; partials reusable
        } else {
            hyw = s;                                  // hy frozen: this is hy @ h2h
        }
    }

    // ---- spiking phase + broadcast of frozen hy/hz (register state, streamed writes) ----
    float u = 0.0f;
    const size_t ob = (size_t)eb * (TSPIKE * NHID) + eh;
    const size_t hb = ((size_t)eb * T_ + THARM) * NHID + eh;
#pragma unroll 4
    for (int t = 0; t < TSPIKE; t++) {
        float spike = (u > THRESH) ? 1.0f : 0.0f;
        if (spike == 1.0f) u = RESET_F;
        float xw = g_xw[((size_t)t << 16) + eidx];
        u = u + ((-u + hyw + xw) * RC_F) * DT_F;
        size_t so = (size_t)t * NHID;
        out_us[ob + so]  = u;
        out_spk[ob + so] = spike;
        out_hys[hb + so] = hy;
        out_hzs[hb + so] = hz;
    }
}

// ---------------- launcher ----------------
extern "C" void kernel_launch(void* const* d_in, const int* in_sizes, int n_in,
                              void* d_out, int out_size) {
    const float* x     = (const float*)d_in[0];
    const float* x2h   = (const float*)d_in[1];
    const float* h2h   = (const float*)d_in[2];
    const float* bias  = (const float*)d_in[3];
    const float* gamma = (const float*)d_in[4];
    const float* eps   = (const float*)d_in[5];

    float* out = (float*)d_out;
    float* out_hys = out;
    float* out_hzs = out + (size_t)B_ * T_ * NHID;
    float* out_us  = out_hzs + (size_t)B_ * T_ * NHID;
    float* out_spk = out_us + (size_t)B_ * TSPIKE * NHID;

    xw_kernel<<<dim3(256, 16), 256>>>(x, x2h);
    ron_kernel<<<NBLK, 256>>>(h2h, bias, gamma, eps,
                              out_hys, out_hzs, out_us, out_spk);
}

// round 14
// speedup vs baseline: 1.6031x; 1.3649x over previous
#include <cuda_runtime.h>
#include <cuda_bf16.h>
#include <cstddef>

// ---------------- problem constants ----------------
#define B_      64
#define T_      512
#define NINP    64
#define NHID    1024
#define THARM   256
#define TSPIKE  256
#define DT_F    0.042f
#define THRESH  0.008f
#define RESET_F 0.001f
#define RC_F    (5.0f * 0.005f)   // R_MEM * C_MEM

// GEMM decomposition: 256 blocks = ks(16) x ct(4) x mt(4)
// tile: 16 b-rows x 256 h-cols x 64 k
#define KS      16
#define KC      64
#define CT      4
#define NT      256
#define MT      16
#define NBLK    256
#define SA_STRIDE 20                 // padded [KC][SA_STRIDE] (16B-aligned rows)
#define PARTSZ  (KS * B_ * NHID)     // 1048576 floats per buffer
#define SMEM_FLOATS (KC * NT + KC * SA_STRIDE)
#define SMEM_BYTES  (SMEM_FLOATS * 4)

// ---------------- device scratch (no cudaMalloc allowed) ----------------
__device__ float g_xw[THARM * B_ * NHID];   // 67 MB: x_t @ x2h, layout [t][b][h]
__device__ float g_part[2 * PARTSZ];        // double-buffered split-K partials (8 MB)
__device__ float g_hyF[B_ * NHID];          // final hy (for t>=256 broadcast)
__device__ float g_hzF[B_ * NHID];          // final hz

// grid-barrier state (replay-safe: sense captured relatively, count self-resets)
__device__ unsigned g_bar_count = 0;
__device__ unsigned g_bar_sense = 0;

__device__ __forceinline__ unsigned ld_acquire_gpu(unsigned* p) {
    unsigned v;
    asm volatile("ld.acquire.gpu.u32 %0, [%1];" : "=r"(v) : "l"(p) : "memory");
    return v;
}
__device__ __forceinline__ unsigned ld_relaxed_gpu(unsigned* p) {
    unsigned v;
    asm volatile("ld.relaxed.gpu.u32 %0, [%1];" : "=r"(v) : "l"(p) : "memory");
    return v;
}
__device__ __forceinline__ unsigned atom_add_release_gpu(unsigned* p, unsigned a) {
    unsigned o;
    asm volatile("atom.add.release.gpu.u32 %0, [%1], %2;" : "=r"(o) : "l"(p), "r"(a) : "memory");
    return o;
}
__device__ __forceinline__ void st_relaxed_gpu(unsigned* p, unsigned v) {
    asm volatile("st.relaxed.gpu.u32 [%0], %1;" :: "l"(p), "r"(v) : "memory");
}

__device__ __forceinline__ void grid_barrier() {
    __syncthreads();
    if (threadIdx.x == 0) {
        unsigned sense = ld_relaxed_gpu(&g_bar_sense);     // capture before arriving
        if (atom_add_release_gpu(&g_bar_count, 1u) == NBLK - 1) {
            st_relaxed_gpu(&g_bar_count, 0u);
            atom_add_release_gpu(&g_bar_sense, 1u);        // release
        } else {
            while (ld_acquire_gpu(&g_bar_sense) == sense) { }
        }
    }
    __syncthreads();
}

// ---------------- packed f32x2 helpers ----------------
__device__ __forceinline__ unsigned long long fma2(unsigned long long a,
                                                   unsigned long long b,
                                                   unsigned long long c) {
    unsigned long long d;
    asm("fma.rn.f32x2 %0, %1, %2, %3;" : "=l"(d) : "l"(a), "l"(b), "l"(c));
    return d;
}
__device__ __forceinline__ unsigned long long pack2(float x, float y) {
    unsigned long long d;
    asm("mov.b64 %0, {%1, %2};" : "=l"(d) : "f"(x), "f"(y));
    return d;
}
__device__ __forceinline__ float2 unpack2(unsigned long long v) {
    float2 f;
    asm("mov.b64 {%0, %1}, %2;" : "=f"(f.x), "=f"(f.y) : "l"(v));
    return f;
}

// ---------------- K0: g_xw[t][b][h] = x[b,t,:] @ x2h[:,h]  (t < 256) ----------------
__global__ void xw_kernel(const float* __restrict__ x, const float* __restrict__ x2h) {
    __shared__ float xs[64][64];   // [row][k]
    __shared__ float ws[64][64];   // [k][c]
    int tid = threadIdx.x;
    int r0 = blockIdx.x * 64;
    int h0 = blockIdx.y * 64;

    for (int i = tid; i < 64 * 16; i += 256) {
        int row = i >> 4, q = i & 15;
        int r = r0 + row;
        int b = r & 63;
        int t = r >> 6;
        ((float4*)xs[row])[q] =
            ((const float4*)(x + (size_t)b * (T_ * NINP) + (size_t)t * NINP))[q];
    }
    for (int i = tid; i < 64 * 16; i += 256) {
        int k = i >> 4, q = i & 15;
        ((float4*)ws[k])[q] = ((const float4*)(x2h + (size_t)k * NHID + h0))[q];
    }
    __syncthreads();

    int tx = tid & 15, ty = tid >> 4;
    float acc[4][4] = {};
#pragma unroll 16
    for (int k = 0; k < 64; k++) {
        float4 bv = ((float4*)ws[k])[tx];
        float a0 = xs[ty * 4 + 0][k];
        float a1 = xs[ty * 4 + 1][k];
        float a2 = xs[ty * 4 + 2][k];
        float a3 = xs[ty * 4 + 3][k];
        acc[0][0] = fmaf(a0, bv.x, acc[0][0]); acc[0][1] = fmaf(a0, bv.y, acc[0][1]);
        acc[0][2] = fmaf(a0, bv.z, acc[0][2]); acc[0][3] = fmaf(a0, bv.w, acc[0][3]);
        acc[1][0] = fmaf(a1, bv.x, acc[1][0]); acc[1][1] = fmaf(a1, bv.y, acc[1][1]);
        acc[1][2] = fmaf(a1, bv.z, acc[1][2]); acc[1][3] = fmaf(a1, bv.w, acc[1][3]);
        acc[2][0] = fmaf(a2, bv.x, acc[2][0]); acc[2][1] = fmaf(a2, bv.y, acc[2][1]);
        acc[2][2] = fmaf(a2, bv.z, acc[2][2]); acc[2][3] = fmaf(a2, bv.w, acc[2][3]);
        acc[3][0] = fmaf(a3, bv.x, acc[3][0]); acc[3][1] = fmaf(a3, bv.y, acc[3][1]);
        acc[3][2] = fmaf(a3, bv.z, acc[3][2]); acc[3][3] = fmaf(a3, bv.w, acc[3][3]);
    }
#pragma unroll
    for (int i = 0; i < 4; i++) {
        float4 v = make_float4(acc[i][0], acc[i][1], acc[i][2], acc[i][3]);
        ((float4*)(g_xw + (size_t)(r0 + ty * 4 + i) * NHID + h0))[tx] = v;
    }
}

// ---------------- persistent kernel: ONE grid barrier per step ----------------
// Block bid: ks = bid&15, ct = (bid>>4)&3, mt = bid>>6.
// GEMM: rows b in [mt*16, +16), cols h in [ct*256, +256), k in [ks*64, +64).
// A slice = exactly the (h,b) elements this block updates (in registers + own smem).
extern "C" __global__ void __launch_bounds__(256, 2) ron_kernel(
        const float* __restrict__ h2h,
        const float* __restrict__ bias,
        const float* __restrict__ gamma,
        const float* __restrict__ eps,
        float* __restrict__ out_hys, float* __restrict__ out_hzs,
        float* __restrict__ out_us,  float* __restrict__ out_spk) {
    extern __shared__ float smem_dyn[];
    float* sb = smem_dyn;                  // [KC][NT]        64 KB, persistent
    float* sa = smem_dyn + KC * NT;        // [KC][SA_STRIDE]  5 KB, hy slice

    const int tid = threadIdx.x, bid = blockIdx.x;
    const int ks = bid & 15;
    const int ct = (bid >> 4) & 3;
    const int mt = bid >> 6;
    const int k0 = ks * KC;
    const int c0 = ct * NT;
    const int b0 = mt * MT;
    const int rg = tid >> 6;       // 0..3: b-rowgroup (4 rows)  [GEMM + update]
    const int cg = tid & 63;       // 0..63: c-colgroup (4 cols) [GEMM]
    const bool writer = (ct == (ks >> 2));   // unique block per (b,h) for output

    // preload h2h slice once: sb[k][h'] = h2h[k0+k][c0+h']
    for (int i = tid; i < KC * NT / 4; i += 256) {
        int k = i >> 6, q = i & 63;
        ((float4*)(sb + k * NT))[q] = ((const float4*)(h2h + (size_t)(k0 + k) * NHID + c0))[q];
    }

    // update mapping: thread owns h = k0 + (tid&63), b = b0 + rg*4 + j (j=0..3)
    const int h2 = tid & 63;
    const int hG = k0 + h2;
    const float bia = __ldg(bias + hG);
    const float gam = __ldg(gamma + hG);
    const float ep  = __ldg(eps + hG);
    float hyr[4], hzr[4];

    // ---- t = 0: hy0 = hz0 = 0 -> recurrent term is 0 ----
#pragma unroll
    for (int j = 0; j < 4; j++) {
        int b = b0 + rg * 4 + j;
        float xw = g_xw[(size_t)b * NHID + hG];
        float z = tanhf(xw + bia);
        float hz = DT_F * z;
        float hy = DT_F * hz;
        hyr[j] = hy; hzr[j] = hz;
        sa[h2 * SA_STRIDE + rg * 4 + j] = hy;
        if (writer) {
            size_t o = ((size_t)b * T_ + 0) * NHID + hG;
            out_hys[o] = hy;
            out_hzs[o] = hz;
        }
    }
    __syncthreads();   // sa + sb ready

    // ---- steps t = 1..255, plus t = 256 producing hyW partials ----
    for (int t = 1; t <= THARM; t++) {
        const int p = t & 1;

        // prefetch xw for this step's update
        float xwj[4];
        if (t < THARM) {
#pragma unroll
            for (int j = 0; j < 4; j++)
                xwj[j] = __ldcg(g_xw + ((size_t)t << 16)
                                + (size_t)(b0 + rg * 4 + j) * NHID + hG);
        }

        // -------- GEMM (A from own smem, B persistent in smem, f32x2) --------
        unsigned long long acc[2][4] = {{0ull,0ull,0ull,0ull},{0ull,0ull,0ull,0ull}};
#pragma unroll 4
        for (int k = 0; k < KC; k++) {
            ulonglong2 au = *reinterpret_cast<const ulonglong2*>(sa + k * SA_STRIDE + rg * 4);
            float4 bv = *reinterpret_cast<const float4*>(sb + k * NT + cg * 4);
            unsigned long long bx = pack2(bv.x, bv.x);
            unsigned long long by = pack2(bv.y, bv.y);
            unsigned long long bz = pack2(bv.z, bv.z);
            unsigned long long bw = pack2(bv.w, bv.w);
            acc[0][0] = fma2(au.x, bx, acc[0][0]); acc[1][0] = fma2(au.y, bx, acc[1][0]);
            acc[0][1] = fma2(au.x, by, acc[0][1]); acc[1][1] = fma2(au.y, by, acc[1][1]);
            acc[0][2] = fma2(au.x, bz, acc[0][2]); acc[1][2] = fma2(au.y, bz, acc[1][2]);
            acc[0][3] = fma2(au.x, bw, acc[0][3]); acc[1][3] = fma2(au.y, bw, acc[1][3]);
        }
        // unpack + store partials (coalesced float4), double-buffered
        {
            float o_[4][4];
#pragma unroll
            for (int bp = 0; bp < 2; bp++)
#pragma unroll
                for (int c = 0; c < 4; c++) {
                    float2 f = unpack2(acc[bp][c]);
                    o_[bp * 2 + 0][c] = f.x;
                    o_[bp * 2 + 1][c] = f.y;
                }
            float* gp = g_part + (size_t)p * PARTSZ + ((size_t)ks << 16)
                        + (size_t)(b0 + rg * 4) * NHID + c0 + cg * 4;
#pragma unroll
            for (int r = 0; r < 4; r++)
                __stcg((float4*)(gp + (size_t)r * NHID),
                       make_float4(o_[r][0], o_[r][1], o_[r][2], o_[r][3]));
        }

        grid_barrier();   // the ONLY global sync per step

        if (t < THARM) {
            // reduce split-K for this block's own A elements (coalesced: warp = 32 h)
            float sum[4] = {0.f, 0.f, 0.f, 0.f};
            const float* pb = g_part + (size_t)p * PARTSZ + hG;
#pragma unroll
            for (int s = 0; s < KS; s++) {
#pragma unroll
                for (int j = 0; j < 4; j++)
                    sum[j] += __ldcg(pb + ((size_t)s << 16)
                                     + (size_t)(b0 + rg * 4 + j) * NHID);
            }
            // update (replicated across ct-peers; identical fp ops -> identical results)
#pragma unroll
            for (int j = 0; j < 4; j++) {
                int b = b0 + rg * 4 + j;
                float z = tanhf(xwj[j] + sum[j] + bia);
                hzr[j] = hzr[j] + DT_F * (z - gam * hyr[j] - ep * hzr[j]);
                hyr[j] = hyr[j] + DT_F * hzr[j];
                sa[h2 * SA_STRIDE + rg * 4 + j] = hyr[j];
                if (writer) {
                    size_t o = ((size_t)b * T_ + t) * NHID + hG;
                    out_hys[o] = hyr[j];
                    out_hzs[o] = hzr[j];
                    if (t == THARM - 1) {
                        __stcg(g_hyF + (size_t)b * NHID + hG, hyr[j]);
                        __stcg(g_hzF + (size_t)b * NHID + hG, hzr[j]);
                    }
                }
            }
            __syncthreads();   // sa complete before next GEMM
        }
    }

    // ---- spiking phase (eidx ownership, coalesced) ----
    const int eidx = (bid << 8) + tid;          // b*1024 + h
    const int eh = eidx & (NHID - 1);
    const int eb = eidx >> 10;
    const int pf = THARM & 1;                   // buffer used by the t=256 pass (=0)
    float hyw = 0.f;
#pragma unroll
    for (int s = 0; s < KS; s++)
        hyw += __ldcg(g_part + (size_t)pf * PARTSZ + ((size_t)s << 16) + eidx);
    float hyE = __ldcg(g_hyF + eidx);
    float hzE = __ldcg(g_hzF + eidx);

    float u = 0.f;
    const size_t ob = (size_t)eb * (TSPIKE * NHID) + eh;
    const size_t hb = ((size_t)eb * T_ + THARM) * NHID + eh;
#pragma unroll 4
    for (int t = 0; t < TSPIKE; t++) {
        float spike = (u > THRESH) ? 1.0f : 0.0f;
        if (spike == 1.0f) u = RESET_F;
        float xw = __ldcg(g_xw + ((size_t)t << 16) + eidx);
        u = u + ((-u + hyw + xw) * RC_F) * DT_F;
        size_t so = (size_t)t * NHID;
        out_us[ob + so]  = u;
        out_spk[ob + so] = spike;
        out_hys[hb + so] = hyE;
        out_hzs[hb + so] = hzE;
    }
}

// ---------------- launcher ----------------
extern "C" void kernel_launch(void* const* d_in, const int* in_sizes, int n_in,
                              void* d_out, int out_size) {
    const float* x     = (const float*)d_in[0];
    const float* x2h   = (const float*)d_in[1];
    const float* h2h   = (const float*)d_in[2];
    const float* bias  = (const float*)d_in[3];
    const float* gamma = (const float*)d_in[4];
    const float* eps   = (const float*)d_in[5];

    float* out = (float*)d_out;
    float* out_hys = out;
    float* out_hzs = out + (size_t)B_ * T_ * NHID;
    float* out_us  = out_hzs + (size_t)B_ * T_ * NHID;
    float* out_spk = out_us + (size_t)B_ * TSPIKE * NHID;

    cudaFuncSetAttribute(ron_kernel, cudaFuncAttributeMaxDynamicSharedMemorySize,
                         SMEM_BYTES);

    xw_kernel<<<dim3(256, 16), 256>>>(x, x2h);
    ron_kernel<<<NBLK, 256, SMEM_BYTES>>>(h2h, bias, gamma, eps,
                                          out_hys, out_hzs, out_us, out_spk);
}